// round 7
// baseline (speedup 1.0000x reference)
#include <cuda_runtime.h>
#include <cuda_bf16.h>
#include <cstdint>

#define N1C 40000
#define N2C 8000
#define E1C 1000000
#define E2C 200000
#define DIN 256
#define HID 256

// ---------------- scratch (device globals: no allocation allowed) ----------
__device__ __align__(16) float g_h1[(size_t)N1C * HID];
__device__ __align__(16) float g_agg[(size_t)N1C * HID];
__device__ __align__(16) __nv_bfloat16 g_Bhi[2 * 512 * 256];
__device__ __align__(16) __nv_bfloat16 g_Blo[2 * 512 * 256];
__device__ __align__(16) int g_hist[N1C + N2C];   // layer1 @0, layer2 @N1C
__device__ int g_off1[N1C + 1];
__device__ int g_cur1[N1C];
__device__ int g_off2[N2C + 1];
__device__ int g_cur2[N2C];
__device__ int g_ss1[E1C];
__device__ int g_ss2[E2C];

// ---------------- helpers ----------------------------------------------------
__device__ __forceinline__ uint32_t smem_u32(const void* p) {
    uint32_t a;
    asm("{ .reg .u64 t; cvta.to.shared.u64 t, %1; cvt.u32.u64 %0, t; }" : "=r"(a) : "l"(p));
    return a;
}
__device__ __forceinline__ void cp16(uint32_t dst, const void* src) {
    asm volatile("cp.async.cg.shared.global [%0], [%1], 16;" :: "r"(dst), "l"(src));
}
#define CP_COMMIT() asm volatile("cp.async.commit_group;" ::: "memory")
__device__ __forceinline__ void ldsm4(uint32_t& r0, uint32_t& r1, uint32_t& r2, uint32_t& r3, uint32_t a) {
    asm volatile("ldmatrix.sync.aligned.m8n8.x4.shared.b16 {%0,%1,%2,%3}, [%4];"
                 : "=r"(r0), "=r"(r1), "=r"(r2), "=r"(r3) : "r"(a));
}
__device__ __forceinline__ void ldsm4t(uint32_t& r0, uint32_t& r1, uint32_t& r2, uint32_t& r3, uint32_t a) {
    asm volatile("ldmatrix.sync.aligned.m8n8.x4.trans.shared.b16 {%0,%1,%2,%3}, [%4];"
                 : "=r"(r0), "=r"(r1), "=r"(r2), "=r"(r3) : "r"(a));
}
__device__ __forceinline__ void mma16816(float* c, const uint32_t* a, const uint32_t* b) {
    asm volatile("mma.sync.aligned.m16n8k16.row.col.f32.bf16.bf16.f32 "
                 "{%0,%1,%2,%3}, {%4,%5,%6,%7}, {%8,%9}, {%0,%1,%2,%3};"
                 : "+f"(c[0]), "+f"(c[1]), "+f"(c[2]), "+f"(c[3])
                 : "r"(a[0]), "r"(a[1]), "r"(a[2]), "r"(a[3]), "r"(b[0]), "r"(b[1]));
}
__device__ __forceinline__ uint32_t pack_bf2(__nv_bfloat16 a, __nv_bfloat16 b) {
    return ((uint32_t)__bfloat16_as_ushort(b) << 16) | (uint32_t)__bfloat16_as_ushort(a);
}
#define STS128(r0, r1, r2, r3, a) asm volatile("st.shared.v4.b32 [%0], {%1,%2,%3,%4};" :: "r"(a), "r"(r0), "r"(r1), "r"(r2), "r"(r3) : "memory")
__device__ __forceinline__ void acc4(float4& A, const float4& v) {
    A.x += v.x; A.y += v.y; A.z += v.z; A.w += v.w;
}

// ---------------- binning kernels (4 edges/thread ILP) --------------------------
__global__ void hist_kernel(const int* __restrict__ dst, int E, int* __restrict__ hist) {
    int i = (blockIdx.x * blockDim.x + threadIdx.x) * 4;
    if (i + 4 <= E) {
        int4 d = __ldg(reinterpret_cast<const int4*>(dst + i));
        atomicAdd(hist + d.x, 1);
        atomicAdd(hist + d.y, 1);
        atomicAdd(hist + d.z, 1);
        atomicAdd(hist + d.w, 1);
    } else {
        for (int j = i; j < E; j++) atomicAdd(hist + __ldg(dst + j), 1);
    }
}

__global__ void scan_kernel(const int* __restrict__ hist, int n,
                            int* __restrict__ off, int* __restrict__ cur) {
    __shared__ int part[1024];
    int t = threadIdx.x;
    int chunk = (n + 1023) >> 10;
    int b = t * chunk;
    int s = 0;
    for (int i = 0; i < chunk; i++) if (b + i < n) s += hist[b + i];
    part[t] = s;
    __syncthreads();
#pragma unroll
    for (int d = 1; d < 1024; d <<= 1) {
        int v = (t >= d) ? part[t - d] : 0;
        __syncthreads();
        part[t] += v;
        __syncthreads();
    }
    int run = (t ? part[t - 1] : 0);
    for (int i = 0; i < chunk; i++) {
        int idx = b + i;
        if (idx < n) { off[idx] = run; cur[idx] = run; run += hist[idx]; }
    }
    if (t == 1023) off[n] = part[1023];
}

__global__ void reorder_kernel(const int* __restrict__ src, const int* __restrict__ dst,
                               int E, int* __restrict__ cur, int* __restrict__ ssrc) {
    int i = (blockIdx.x * blockDim.x + threadIdx.x) * 4;
    if (i + 4 <= E) {
        int4 d = __ldg(reinterpret_cast<const int4*>(dst + i));
        int4 s = __ldg(reinterpret_cast<const int4*>(src + i));
        int p0 = atomicAdd(cur + d.x, 1);
        int p1 = atomicAdd(cur + d.y, 1);
        int p2 = atomicAdd(cur + d.z, 1);
        int p3 = atomicAdd(cur + d.w, 1);
        ssrc[p0] = s.x; ssrc[p1] = s.y; ssrc[p2] = s.z; ssrc[p3] = s.w;
    } else {
        for (int j = i; j < E; j++) {
            int pos = atomicAdd(cur + __ldg(dst + j), 1);
            ssrc[pos] = __ldg(src + j);
        }
    }
}

// ---------------- segmented gather-mean (fp32 out, inv folded, 8-unroll) --------
__global__ __launch_bounds__(256)
void agg_mean(const float* __restrict__ x,
              const int* __restrict__ ssrc, const int* __restrict__ off,
              float* __restrict__ agg, int n_tgt) {
    int w = (blockIdx.x * blockDim.x + threadIdx.x) >> 5;
    if (w >= n_tgt) return;
    int lane = threadIdx.x & 31;
    int s0 = __ldg(off + w), s1 = __ldg(off + w + 1);

    float4 A0 = make_float4(0.f, 0.f, 0.f, 0.f);
    float4 A1 = make_float4(0.f, 0.f, 0.f, 0.f);
    int e = s0;
    for (; e + 8 <= s1; e += 8) {
        int si[8];
#pragma unroll
        for (int j = 0; j < 8; j++) si[j] = __ldg(ssrc + e + j);
        float4 v0[8], v1[8];
#pragma unroll
        for (int j = 0; j < 8; j++) {
            const float4* p = reinterpret_cast<const float4*>(x) + (size_t)si[j] * 64;
            v0[j] = __ldg(p + lane);
            v1[j] = __ldg(p + lane + 32);
        }
#pragma unroll
        for (int j = 0; j < 8; j++) { acc4(A0, v0[j]); acc4(A1, v1[j]); }
    }
    for (; e + 2 <= s1; e += 2) {
        int sa = __ldg(ssrc + e), sb = __ldg(ssrc + e + 1);
        const float4* pa = reinterpret_cast<const float4*>(x) + (size_t)sa * 64;
        const float4* pb = reinterpret_cast<const float4*>(x) + (size_t)sb * 64;
        float4 a0 = __ldg(pa + lane), a1 = __ldg(pa + lane + 32);
        float4 b0 = __ldg(pb + lane), b1 = __ldg(pb + lane + 32);
        acc4(A0, a0); acc4(A0, b0);
        acc4(A1, a1); acc4(A1, b1);
    }
    if (e < s1) {
        int sa = __ldg(ssrc + e);
        const float4* pa = reinterpret_cast<const float4*>(x) + (size_t)sa * 64;
        float4 a0 = __ldg(pa + lane), a1 = __ldg(pa + lane + 32);
        acc4(A0, a0); acc4(A1, a1);
    }
    float inv = 1.0f / fmaxf((float)(s1 - s0), 1.0f);
    A0.x *= inv; A0.y *= inv; A0.z *= inv; A0.w *= inv;
    A1.x *= inv; A1.y *= inv; A1.z *= inv; A1.w *= inv;

    float4* op = reinterpret_cast<float4*>(agg) + (size_t)w * 64;
    op[lane] = A0;
    op[lane + 32] = A1;
}

// ---------------- B pack --------------------------------------------------------
__global__ void pack_B(const float* __restrict__ Wl1, const float* __restrict__ Wr1,
                       const float* __restrict__ Wl2, const float* __restrict__ Wr2,
                       __nv_bfloat16* __restrict__ Bhi, __nv_bfloat16* __restrict__ Blo) {
    int idx = blockIdx.x * blockDim.x + threadIdx.x;  // 2*512*64
    if (idx >= 2 * 512 * 64) return;
    int l = idx >> 15;
    int k = (idx >> 6) & 511;
    int col = (idx & 63) * 4;
    const float* W = (l == 0) ? ((k < 256) ? Wl1 : Wr1) : ((k < 256) ? Wl2 : Wr2);
    float4 v = __ldg(reinterpret_cast<const float4*>(W + (size_t)(k & 255) * 256 + col));
    __nv_bfloat16 h0 = __float2bfloat16(v.x), h1 = __float2bfloat16(v.y);
    __nv_bfloat16 h2 = __float2bfloat16(v.z), h3 = __float2bfloat16(v.w);
    __nv_bfloat16 l0 = __float2bfloat16(v.x - __bfloat162float(h0));
    __nv_bfloat16 l1 = __float2bfloat16(v.y - __bfloat162float(h1));
    __nv_bfloat16 l2 = __float2bfloat16(v.z - __bfloat162float(h2));
    __nv_bfloat16 l3 = __float2bfloat16(v.w - __bfloat162float(h3));
    size_t o = ((size_t)l * 512 + k) * 256 + col;
    *reinterpret_cast<uint2*>(Bhi + o) = make_uint2(pack_bf2(h0, h1), pack_bf2(h2, h3));
    *reinterpret_cast<uint2*>(Blo + o) = make_uint2(pack_bf2(l0, l1), pack_bf2(l2, l3));
}

// ---------------- single-pass interleaved 3-phase GEMM + bias + PReLU ----------
#define FBM 64
#define FBN 128

__global__ __launch_bounds__(256, 2)
void gemm_fused2(const float* __restrict__ Asrc0, const float* __restrict__ Asrc1,
                 const __nv_bfloat16* __restrict__ Bhi, const __nv_bfloat16* __restrict__ Blo,
                 const float* __restrict__ bias, const float* __restrict__ alpha,
                 float* __restrict__ out, int M) {
    extern __shared__ char smem[];
    uint32_t sb = smem_u32(smem);
    const uint32_t sAhi = sb, sAlo = sb + 8192u, sBB = sb + 16384u;
    const int tid = threadIdx.x;
    const int wid = tid >> 5, lane = tid & 31;
    const int bm = blockIdx.x * FBM;
    const int bn = blockIdx.y * FBN;
    const int m0 = (wid & 1) * 32;
    const int n0 = (wid >> 1) * 32;

    float acc[2][4][4];
#pragma unroll
    for (int i = 0; i < 2; i++)
#pragma unroll
        for (int j = 0; j < 4; j++)
#pragma unroll
            for (int r = 0; r < 4; r++) acc[i][j][r] = 0.0f;

    const int ar = tid >> 2;
    const int acs = (tid & 3) * 16;
    const int grow = bm + ar;
    float av[16];

#define LD_A(c) do { \
        const float* _b = ((c) < 4) ? (Asrc0 + (c) * 64) : (Asrc1 + ((c) - 4) * 64); \
        if (grow < M) { \
            _Pragma("unroll") \
            for (int q = 0; q < 4; q++) { \
                float4 f = __ldg(reinterpret_cast<const float4*>(_b + (size_t)grow * 256 + acs) + q); \
                av[q * 4 + 0] = f.x; av[q * 4 + 1] = f.y; av[q * 4 + 2] = f.z; av[q * 4 + 3] = f.w; \
            } \
        } else { \
            _Pragma("unroll") \
            for (int q = 0; q < 16; q++) av[q] = 0.0f; \
        } \
    } while (0)

#define ST_A() do { \
        _Pragma("unroll") \
        for (int p = 0; p < 2; p++) { \
            uint32_t hi[4], lo[4]; \
            _Pragma("unroll") \
            for (int j = 0; j < 4; j++) { \
                float a0 = av[p * 8 + j * 2], a1 = av[p * 8 + j * 2 + 1]; \
                __nv_bfloat16 h0 = __float2bfloat16(a0), h1 = __float2bfloat16(a1); \
                __nv_bfloat16 l0 = __float2bfloat16(a0 - __bfloat162float(h0)); \
                __nv_bfloat16 l1 = __float2bfloat16(a1 - __bfloat162float(h1)); \
                hi[j] = pack_bf2(h0, h1); lo[j] = pack_bf2(l0, l1); \
            } \
            uint32_t off = (((uint32_t)ar * 128u + (uint32_t)acs * 2u + (uint32_t)p * 16u) ^ (((uint32_t)ar & 7u) << 4)); \
            STS128(hi[0], hi[1], hi[2], hi[3], sAhi + off); \
            STS128(lo[0], lo[1], lo[2], lo[3], sAlo + off); \
        } \
    } while (0)

#define LD_B(c, buf) do { \
        const __nv_bfloat16* _ph = Bhi + (size_t)((c) * 64) * 256 + bn; \
        const __nv_bfloat16* _pl = Blo + (size_t)((c) * 64) * 256 + bn; \
        uint32_t _dh = sBB + (uint32_t)(buf) * 32768u; \
        uint32_t _dl = _dh + 16384u; \
        _Pragma("unroll") \
        for (int i = 0; i < 4; i++) { \
            int row = (tid >> 4) + i * 16; \
            int seg = tid & 15; \
            uint32_t off = (((uint32_t)row * 256u + (uint32_t)seg * 16u) ^ (((uint32_t)row & 7u) << 4)); \
            cp16(_dh + off, _ph + (size_t)row * 256 + seg * 8); \
            cp16(_dl + off, _pl + (size_t)row * 256 + seg * 8); \
        } \
        CP_COMMIT(); \
    } while (0)

    LD_B(0, 0);
    LD_A(0);
    ST_A();
    LD_A(1);

#pragma unroll 1
    for (int c = 0; c < 8; c++) {
        const int buf = c & 1;
        if (c + 1 < 8) {
            LD_B(c + 1, buf ^ 1);
            asm volatile("cp.async.wait_group 1;" ::: "memory");
        } else {
            asm volatile("cp.async.wait_group 0;" ::: "memory");
        }
        __syncthreads();

        const uint32_t bhb = sBB + (uint32_t)buf * 32768u;
        const uint32_t blb = bhb + 16384u;
#pragma unroll
        for (int ks = 0; ks < 4; ks++) {
            uint32_t ahi[2][4], alo[2][4];
#pragma unroll
            for (int i = 0; i < 2; i++) {
                uint32_t mrow = (uint32_t)(m0 + i * 16 + (lane & 15));
                uint32_t kb = (uint32_t)(ks * 32 + (lane >> 4) * 16);
                uint32_t off = ((mrow * 128u + kb) ^ ((mrow & 7u) << 4));
                ldsm4(ahi[i][0], ahi[i][1], ahi[i][2], ahi[i][3], sAhi + off);
                ldsm4(alo[i][0], alo[i][1], alo[i][2], alo[i][3], sAlo + off);
            }
            uint32_t bh[4][2], bl[4][2];
#pragma unroll
            for (int j2 = 0; j2 < 2; j2++) {
                uint32_t krow = (uint32_t)(ks * 16 + (lane & 15));
                uint32_t cb = (uint32_t)((n0 + j2 * 16 + (lane >> 4) * 8) * 2);
                uint32_t off = ((krow * 256u + cb) ^ ((krow & 7u) << 4));
                ldsm4t(bh[j2 * 2][0], bh[j2 * 2][1], bh[j2 * 2 + 1][0], bh[j2 * 2 + 1][1], bhb + off);
                ldsm4t(bl[j2 * 2][0], bl[j2 * 2][1], bl[j2 * 2 + 1][0], bl[j2 * 2 + 1][1], blb + off);
            }
#pragma unroll
            for (int i = 0; i < 2; i++)
#pragma unroll
                for (int j = 0; j < 4; j++) {
                    mma16816(acc[i][j], ahi[i], bh[j]);
                    mma16816(acc[i][j], ahi[i], bl[j]);
                    mma16816(acc[i][j], alo[i], bh[j]);
                }
        }
        __syncthreads();

        if (c + 1 < 8) {
            ST_A();
            if (c + 2 < 8) LD_A(c + 2);
        }
    }

#pragma unroll
    for (int i = 0; i < 2; i++) {
        int r0 = bm + m0 + i * 16 + (lane >> 2);
#pragma unroll
        for (int j = 0; j < 4; j++) {
            int col = bn + n0 + j * 8 + (lane & 3) * 2;
            float2 bb = __ldg(reinterpret_cast<const float2*>(bias + col));
            float2 aa = __ldg(reinterpret_cast<const float2*>(alpha + col));
            if (r0 < M) {
                float v0 = acc[i][j][0] + bb.x;
                float v1 = acc[i][j][1] + bb.y;
                v0 = v0 > 0.f ? v0 : aa.x * v0;
                v1 = v1 > 0.f ? v1 : aa.y * v1;
                *reinterpret_cast<float2*>(out + (size_t)r0 * 256 + col) = make_float2(v0, v1);
            }
            if (r0 + 8 < M) {
                float v2 = acc[i][j][2] + bb.x;
                float v3 = acc[i][j][3] + bb.y;
                v2 = v2 > 0.f ? v2 : aa.x * v2;
                v3 = v3 > 0.f ? v3 : aa.y * v3;
                *reinterpret_cast<float2*>(out + (size_t)(r0 + 8) * 256 + col) = make_float2(v2, v3);
            }
        }
    }
#undef LD_A
#undef ST_A
#undef LD_B
}

// ---------------- launch -------------------------------------------------------
extern "C" void kernel_launch(void* const* d_in, const int* in_sizes, int n_in,
                              void* d_out, int out_size) {
    const float* x    = (const float*)d_in[0];
    const int*   src1 = (const int*)d_in[1];
    const int*   dst1 = (const int*)d_in[2];
    const int*   src2 = (const int*)d_in[3];
    const int*   dst2 = (const int*)d_in[4];

    int iW = 5;
    while (iW < n_in && in_sizes[iW] != DIN * HID) iW++;
    const float* W_l1 = (const float*)d_in[iW + 0];
    const float* W_r1 = (const float*)d_in[iW + 1];
    const float* b1   = (const float*)d_in[iW + 2];
    const float* a1   = (const float*)d_in[iW + 3];
    const float* W_l2 = (const float*)d_in[iW + 4];
    const float* W_r2 = (const float*)d_in[iW + 5];
    const float* b2   = (const float*)d_in[iW + 6];
    const float* a2   = (const float*)d_in[iW + 7];

    const int E1 = in_sizes[1];
    const int E2 = in_sizes[3];

    float *h1, *agg;
    __nv_bfloat16 *Bhi, *Blo;
    int *hist, *off1, *cur1, *off2, *cur2, *ss1, *ss2;
    cudaGetSymbolAddress((void**)&h1,   g_h1);
    cudaGetSymbolAddress((void**)&agg,  g_agg);
    cudaGetSymbolAddress((void**)&Bhi,  g_Bhi);
    cudaGetSymbolAddress((void**)&Blo,  g_Blo);
    cudaGetSymbolAddress((void**)&hist, g_hist);
    cudaGetSymbolAddress((void**)&off1, g_off1);
    cudaGetSymbolAddress((void**)&cur1, g_cur1);
    cudaGetSymbolAddress((void**)&off2, g_off2);
    cudaGetSymbolAddress((void**)&cur2, g_cur2);
    cudaGetSymbolAddress((void**)&ss1,  g_ss1);
    cudaGetSymbolAddress((void**)&ss2,  g_ss2);

    float* out = (float*)d_out;

    const int SMEM_GEMM = 16384 + 2 * 32768;   // 80KB
    cudaFuncSetAttribute(gemm_fused2, cudaFuncAttributeMaxDynamicSharedMemorySize, SMEM_GEMM);

    const int E4 = 256 * 4;  // elements per block in 4-way kernels

    // launch index:                                           // idx
    cudaMemsetAsync(hist, 0, (N1C + N2C) * sizeof(int));       // 0
    hist_kernel<<<(E1 + E4 - 1) / E4, 256>>>(dst1, E1, hist);  // 1
    scan_kernel<<<1, 1024>>>(hist, N1C, off1, cur1);           // 2
    reorder_kernel<<<(E1 + E4 - 1) / E4, 256>>>(src1, dst1, E1, cur1, ss1);  // 3
    agg_mean<<<(N1C + 7) / 8, 256>>>(x, ss1, off1, agg, N1C);  // 4  <-- ncu window
    pack_B<<<(2 * 512 * 64 + 255) / 256, 256>>>(W_l1, W_r1, W_l2, W_r2, Bhi, Blo);  // 5
    {
        dim3 grid((N1C + FBM - 1) / FBM, 2);                   // 6
        gemm_fused2<<<grid, 256, SMEM_GEMM>>>(agg, x, Bhi, Blo, b1, a1, h1, N1C);
    }

    // ---------------- layer 2 ----------------
    hist_kernel<<<(E2 + E4 - 1) / E4, 256>>>(dst2, E2, hist + N1C);            // 7
    scan_kernel<<<1, 1024>>>(hist + N1C, N2C, off2, cur2);                     // 8
    reorder_kernel<<<(E2 + E4 - 1) / E4, 256>>>(src2, dst2, E2, cur2, ss2);    // 9
    agg_mean<<<(N2C + 7) / 8, 256>>>(h1, ss2, off2, agg, N2C);                 // 10
    {
        dim3 grid((N2C + FBM - 1) / FBM, 2);                                   // 11
        gemm_fused2<<<grid, 256, SMEM_GEMM>>>(agg, h1, Bhi + 512 * 256, Blo + 512 * 256, b2, a2, out, N2C);
    }
}

// round 8
// speedup vs baseline: 1.1292x; 1.1292x over previous
#include <cuda_runtime.h>
#include <cuda_fp16.h>
#include <cstdint>

#define N1C 40000
#define N2C 8000
#define E1C 1000000
#define E2C 200000
#define DIN 256
#define HID 256

// ---------------- scratch (device globals: no allocation allowed) ----------
__device__ __align__(16) float g_h1[(size_t)N1C * HID];
__device__ __align__(16) __half g_A[(size_t)N1C * 512];     // [row][k]: 0-255 mean, 256-511 root
__device__ __align__(16) __half g_Bhi[2 * 512 * 256];
__device__ __align__(16) __half g_Blo[2 * 512 * 256];
__device__ __align__(16) int g_hist[N1C + N2C];
__device__ int g_off1[N1C + 1];
__device__ int g_cur1[N1C];
__device__ int g_off2[N2C + 1];
__device__ int g_cur2[N2C];
__device__ int g_ss1[E1C];
__device__ int g_ss2[E2C];

// ---------------- helpers ----------------------------------------------------
__device__ __forceinline__ uint32_t smem_u32(const void* p) {
    uint32_t a;
    asm("{ .reg .u64 t; cvta.to.shared.u64 t, %1; cvt.u32.u64 %0, t; }" : "=r"(a) : "l"(p));
    return a;
}
__device__ __forceinline__ void cp16p(uint32_t dst, const void* src, bool pred) {
    int n = pred ? 16 : 0;
    asm volatile("cp.async.cg.shared.global [%0], [%1], 16, %2;" :: "r"(dst), "l"(src), "r"(n));
}
#define CP_COMMIT() asm volatile("cp.async.commit_group;" ::: "memory")
__device__ __forceinline__ void ldsm4(uint32_t& r0, uint32_t& r1, uint32_t& r2, uint32_t& r3, uint32_t a) {
    asm volatile("ldmatrix.sync.aligned.m8n8.x4.shared.b16 {%0,%1,%2,%3}, [%4];"
                 : "=r"(r0), "=r"(r1), "=r"(r2), "=r"(r3) : "r"(a));
}
__device__ __forceinline__ void ldsm4t(uint32_t& r0, uint32_t& r1, uint32_t& r2, uint32_t& r3, uint32_t a) {
    asm volatile("ldmatrix.sync.aligned.m8n8.x4.trans.shared.b16 {%0,%1,%2,%3}, [%4];"
                 : "=r"(r0), "=r"(r1), "=r"(r2), "=r"(r3) : "r"(a));
}
__device__ __forceinline__ void mma16816h(float* c, const uint32_t* a, const uint32_t* b) {
    asm volatile("mma.sync.aligned.m16n8k16.row.col.f32.f16.f16.f32 "
                 "{%0,%1,%2,%3}, {%4,%5,%6,%7}, {%8,%9}, {%0,%1,%2,%3};"
                 : "+f"(c[0]), "+f"(c[1]), "+f"(c[2]), "+f"(c[3])
                 : "r"(a[0]), "r"(a[1]), "r"(a[2]), "r"(a[3]), "r"(b[0]), "r"(b[1]));
}
__device__ __forceinline__ uint32_t f2h2(float a, float b) {
    __half2 h = __floats2half2_rn(a, b);
    return *reinterpret_cast<uint32_t*>(&h);
}
__device__ __forceinline__ void acc4(float4& A, const float4& v) {
    A.x += v.x; A.y += v.y; A.z += v.z; A.w += v.w;
}

// ---------------- binning kernels (4 edges/thread ILP) --------------------------
__global__ void hist_kernel(const int* __restrict__ dst, int E, int* __restrict__ hist) {
    int i = (blockIdx.x * blockDim.x + threadIdx.x) * 4;
    if (i + 4 <= E) {
        int4 d = __ldg(reinterpret_cast<const int4*>(dst + i));
        atomicAdd(hist + d.x, 1);
        atomicAdd(hist + d.y, 1);
        atomicAdd(hist + d.z, 1);
        atomicAdd(hist + d.w, 1);
    } else {
        for (int j = i; j < E; j++) atomicAdd(hist + __ldg(dst + j), 1);
    }
}

__global__ void scan_kernel(const int* __restrict__ hist, int n,
                            int* __restrict__ off, int* __restrict__ cur) {
    __shared__ int part[1024];
    int t = threadIdx.x;
    int chunk = (n + 1023) >> 10;
    int b = t * chunk;
    int s = 0;
    for (int i = 0; i < chunk; i++) if (b + i < n) s += hist[b + i];
    part[t] = s;
    __syncthreads();
#pragma unroll
    for (int d = 1; d < 1024; d <<= 1) {
        int v = (t >= d) ? part[t - d] : 0;
        __syncthreads();
        part[t] += v;
        __syncthreads();
    }
    int run = (t ? part[t - 1] : 0);
    for (int i = 0; i < chunk; i++) {
        int idx = b + i;
        if (idx < n) { off[idx] = run; cur[idx] = run; run += hist[idx]; }
    }
    if (t == 1023) off[n] = part[1023];
}

__global__ void reorder_kernel(const int* __restrict__ src, const int* __restrict__ dst,
                               int E, int* __restrict__ cur, int* __restrict__ ssrc) {
    int i = (blockIdx.x * blockDim.x + threadIdx.x) * 4;
    if (i + 4 <= E) {
        int4 d = __ldg(reinterpret_cast<const int4*>(dst + i));
        int4 s = __ldg(reinterpret_cast<const int4*>(src + i));
        int p0 = atomicAdd(cur + d.x, 1);
        int p1 = atomicAdd(cur + d.y, 1);
        int p2 = atomicAdd(cur + d.z, 1);
        int p3 = atomicAdd(cur + d.w, 1);
        ssrc[p0] = s.x; ssrc[p1] = s.y; ssrc[p2] = s.z; ssrc[p3] = s.w;
    } else {
        for (int j = i; j < E; j++) {
            int pos = atomicAdd(cur + __ldg(dst + j), 1);
            ssrc[pos] = __ldg(src + j);
        }
    }
}

// ---------------- segmented gather-mean -> packed fp16 A operand ---------------
// A[w][0:256)  = fp16( mean_{e in seg} x[src_e] )
// A[w][256:512)= fp16( xroot[w] )
__global__ __launch_bounds__(256)
void agg_mean(const float* __restrict__ x, const float* __restrict__ xroot,
              const int* __restrict__ ssrc, const int* __restrict__ off,
              __half* __restrict__ A, int n_tgt) {
    int w = (blockIdx.x * blockDim.x + threadIdx.x) >> 5;
    if (w >= n_tgt) return;
    int lane = threadIdx.x & 31;
    int s0 = __ldg(off + w), s1 = __ldg(off + w + 1);

    float4 A0 = make_float4(0.f, 0.f, 0.f, 0.f);
    float4 A1 = make_float4(0.f, 0.f, 0.f, 0.f);
    int e = s0;
    for (; e + 4 <= s1; e += 4) {
        int sa = __ldg(ssrc + e), sb = __ldg(ssrc + e + 1);
        int sc = __ldg(ssrc + e + 2), sd = __ldg(ssrc + e + 3);
        const float4* pa = reinterpret_cast<const float4*>(x) + (size_t)sa * 64;
        const float4* pb = reinterpret_cast<const float4*>(x) + (size_t)sb * 64;
        const float4* pc = reinterpret_cast<const float4*>(x) + (size_t)sc * 64;
        const float4* pd = reinterpret_cast<const float4*>(x) + (size_t)sd * 64;
        float4 a0 = __ldg(pa + lane), a1 = __ldg(pa + lane + 32);
        float4 b0 = __ldg(pb + lane), b1 = __ldg(pb + lane + 32);
        float4 c0 = __ldg(pc + lane), c1 = __ldg(pc + lane + 32);
        float4 d0 = __ldg(pd + lane), d1 = __ldg(pd + lane + 32);
        acc4(A0, a0); acc4(A0, b0); acc4(A0, c0); acc4(A0, d0);
        acc4(A1, a1); acc4(A1, b1); acc4(A1, c1); acc4(A1, d1);
    }
    for (; e < s1; e++) {
        int sa = __ldg(ssrc + e);
        const float4* pa = reinterpret_cast<const float4*>(x) + (size_t)sa * 64;
        float4 a0 = __ldg(pa + lane), a1 = __ldg(pa + lane + 32);
        acc4(A0, a0); acc4(A1, a1);
    }
    float inv = 1.0f / fmaxf((float)(s1 - s0), 1.0f);
    A0.x *= inv; A0.y *= inv; A0.z *= inv; A0.w *= inv;
    A1.x *= inv; A1.y *= inv; A1.z *= inv; A1.w *= inv;

    const float4* px = reinterpret_cast<const float4*>(xroot) + (size_t)w * 64;
    float4 X0 = __ldg(px + lane), X1 = __ldg(px + lane + 32);

    __half* rp = A + (size_t)w * 512 + lane * 4;
    *reinterpret_cast<uint2*>(rp)       = make_uint2(f2h2(A0.x, A0.y), f2h2(A0.z, A0.w));
    *reinterpret_cast<uint2*>(rp + 128) = make_uint2(f2h2(A1.x, A1.y), f2h2(A1.z, A1.w));
    *reinterpret_cast<uint2*>(rp + 256) = make_uint2(f2h2(X0.x, X0.y), f2h2(X0.z, X0.w));
    *reinterpret_cast<uint2*>(rp + 384) = make_uint2(f2h2(X1.x, X1.y), f2h2(X1.z, X1.w));
}

// ---------------- B pack (fp16 hi/lo split) -------------------------------------
__global__ void pack_B(const float* __restrict__ Wl1, const float* __restrict__ Wr1,
                       const float* __restrict__ Wl2, const float* __restrict__ Wr2,
                       __half* __restrict__ Bhi, __half* __restrict__ Blo) {
    int idx = blockIdx.x * blockDim.x + threadIdx.x;  // 2*512*64
    if (idx >= 2 * 512 * 64) return;
    int l = idx >> 15;
    int k = (idx >> 6) & 511;
    int col = (idx & 63) * 4;
    const float* W = (l == 0) ? ((k < 256) ? Wl1 : Wr1) : ((k < 256) ? Wl2 : Wr2);
    float4 v = __ldg(reinterpret_cast<const float4*>(W + (size_t)(k & 255) * 256 + col));
    __half h0 = __float2half_rn(v.x), h1 = __float2half_rn(v.y);
    __half h2 = __float2half_rn(v.z), h3 = __float2half_rn(v.w);
    float l0 = v.x - __half2float(h0), l1 = v.y - __half2float(h1);
    float l2 = v.z - __half2float(h2), l3 = v.w - __half2float(h3);
    size_t o = ((size_t)l * 512 + k) * 256 + col;
    *reinterpret_cast<uint2*>(Bhi + o) = make_uint2(f2h2(__half2float(h0), __half2float(h1)),
                                                    f2h2(__half2float(h2), __half2float(h3)));
    *reinterpret_cast<uint2*>(Blo + o) = make_uint2(f2h2(l0, l1), f2h2(l2, l3));
}

// ---------------- fp16 2-combo GEMM + bias + PReLU -----------------------------
// out[m,n] = prelu( sum_k A[m,k]*(Bhi+Blo)[k,n] + bias[n], alpha[n] )
// BM=64, BN=128, BK=64, K=512 (8 chunks), A single fp16, B hi/lo fp16.
#define FBM 64
#define FBN 128

__global__ __launch_bounds__(256, 2)
void gemm_fp16(const __half* __restrict__ A,
               const __half* __restrict__ Bhi, const __half* __restrict__ Blo,
               const float* __restrict__ bias, const float* __restrict__ alpha,
               float* __restrict__ out, int M) {
    extern __shared__ char smem[];
    uint32_t sb = smem_u32(smem);
    const uint32_t sA = sb;              // 2 x 8KB
    const uint32_t sB = sb + 16384u;     // 2 x 32KB (hi 16K + lo 16K each)
    const int tid = threadIdx.x;
    const int wid = tid >> 5, lane = tid & 31;
    const int bm = blockIdx.x * FBM;
    const int bn = blockIdx.y * FBN;
    const int m0 = (wid & 1) * 32;
    const int n0 = (wid >> 1) * 32;

    float acc[2][4][4];
#pragma unroll
    for (int i = 0; i < 2; i++)
#pragma unroll
        for (int j = 0; j < 4; j++)
#pragma unroll
            for (int r = 0; r < 4; r++) acc[i][j][r] = 0.0f;

    const int arow = tid >> 2, aq = tid & 3;
    const bool arok = (bm + arow) < M;

#define LD_AB(c, buf) do { \
        const __half* _sa = A + (size_t)(bm + arow) * 512 + (c) * 64 + aq * 8; \
        uint32_t _da = sA + (uint32_t)(buf) * 8192u; \
        uint32_t _o1 = (((uint32_t)arow * 128u + (uint32_t)aq * 16u) ^ (((uint32_t)arow & 7u) << 4)); \
        uint32_t _o2 = (((uint32_t)arow * 128u + (uint32_t)(aq + 4) * 16u) ^ (((uint32_t)arow & 7u) << 4)); \
        cp16p(_da + _o1, _sa, arok); \
        cp16p(_da + _o2, _sa + 32, arok); \
        const __half* _ph = Bhi + (size_t)((c) * 64) * 256 + bn; \
        const __half* _pl = Blo + (size_t)((c) * 64) * 256 + bn; \
        uint32_t _dh = sB + (uint32_t)(buf) * 32768u; \
        uint32_t _dl = _dh + 16384u; \
        _Pragma("unroll") \
        for (int i = 0; i < 4; i++) { \
            int row = (tid >> 4) + i * 16; \
            int seg = tid & 15; \
            uint32_t off = (((uint32_t)row * 256u + (uint32_t)seg * 16u) ^ (((uint32_t)row & 7u) << 4)); \
            cp16p(_dh + off, _ph + (size_t)row * 256 + seg * 8, true); \
            cp16p(_dl + off, _pl + (size_t)row * 256 + seg * 8, true); \
        } \
        CP_COMMIT(); \
    } while (0)

    LD_AB(0, 0);

#pragma unroll 1
    for (int c = 0; c < 8; c++) {
        const int buf = c & 1;
        if (c + 1 < 8) {
            LD_AB(c + 1, buf ^ 1);
            asm volatile("cp.async.wait_group 1;" ::: "memory");
        } else {
            asm volatile("cp.async.wait_group 0;" ::: "memory");
        }
        __syncthreads();

        const uint32_t ab = sA + (uint32_t)buf * 8192u;
        const uint32_t bhb = sB + (uint32_t)buf * 32768u;
        const uint32_t blb = bhb + 16384u;
#pragma unroll
        for (int ks = 0; ks < 4; ks++) {
            uint32_t a[2][4];
#pragma unroll
            for (int i = 0; i < 2; i++) {
                uint32_t mrow = (uint32_t)(m0 + i * 16 + (lane & 15));
                uint32_t kb = (uint32_t)(ks * 32 + (lane >> 4) * 16);
                uint32_t off = ((mrow * 128u + kb) ^ ((mrow & 7u) << 4));
                ldsm4(a[i][0], a[i][1], a[i][2], a[i][3], ab + off);
            }
            uint32_t bh[4][2], bl[4][2];
#pragma unroll
            for (int j2 = 0; j2 < 2; j2++) {
                uint32_t krow = (uint32_t)(ks * 16 + (lane & 15));
                uint32_t cb = (uint32_t)((n0 + j2 * 16 + (lane >> 4) * 8) * 2);
                uint32_t off = ((krow * 256u + cb) ^ ((krow & 7u) << 4));
                ldsm4t(bh[j2 * 2][0], bh[j2 * 2][1], bh[j2 * 2 + 1][0], bh[j2 * 2 + 1][1], bhb + off);
                ldsm4t(bl[j2 * 2][0], bl[j2 * 2][1], bl[j2 * 2 + 1][0], bl[j2 * 2 + 1][1], blb + off);
            }
#pragma unroll
            for (int i = 0; i < 2; i++)
#pragma unroll
                for (int j = 0; j < 4; j++) {
                    mma16816h(acc[i][j], a[i], bh[j]);
                    mma16816h(acc[i][j], a[i], bl[j]);
                }
        }
        __syncthreads();
    }

    // ---- epilogue: bias + PReLU + store ----
#pragma unroll
    for (int i = 0; i < 2; i++) {
        int r0 = bm + m0 + i * 16 + (lane >> 2);
#pragma unroll
        for (int j = 0; j < 4; j++) {
            int col = bn + n0 + j * 8 + (lane & 3) * 2;
            float2 bb = __ldg(reinterpret_cast<const float2*>(bias + col));
            float2 aa = __ldg(reinterpret_cast<const float2*>(alpha + col));
            if (r0 < M) {
                float v0 = acc[i][j][0] + bb.x;
                float v1 = acc[i][j][1] + bb.y;
                v0 = v0 > 0.f ? v0 : aa.x * v0;
                v1 = v1 > 0.f ? v1 : aa.y * v1;
                *reinterpret_cast<float2*>(out + (size_t)r0 * 256 + col) = make_float2(v0, v1);
            }
            if (r0 + 8 < M) {
                float v2 = acc[i][j][2] + bb.x;
                float v3 = acc[i][j][3] + bb.y;
                v2 = v2 > 0.f ? v2 : aa.x * v2;
                v3 = v3 > 0.f ? v3 : aa.y * v3;
                *reinterpret_cast<float2*>(out + (size_t)(r0 + 8) * 256 + col) = make_float2(v2, v3);
            }
        }
    }
#undef LD_AB
}

// ---------------- launch -------------------------------------------------------
extern "C" void kernel_launch(void* const* d_in, const int* in_sizes, int n_in,
                              void* d_out, int out_size) {
    const float* x    = (const float*)d_in[0];
    const int*   src1 = (const int*)d_in[1];
    const int*   dst1 = (const int*)d_in[2];
    const int*   src2 = (const int*)d_in[3];
    const int*   dst2 = (const int*)d_in[4];

    int iW = 5;
    while (iW < n_in && in_sizes[iW] != DIN * HID) iW++;
    const float* W_l1 = (const float*)d_in[iW + 0];
    const float* W_r1 = (const float*)d_in[iW + 1];
    const float* b1   = (const float*)d_in[iW + 2];
    const float* a1   = (const float*)d_in[iW + 3];
    const float* W_l2 = (const float*)d_in[iW + 4];
    const float* W_r2 = (const float*)d_in[iW + 5];
    const float* b2   = (const float*)d_in[iW + 6];
    const float* a2   = (const float*)d_in[iW + 7];

    const int E1 = in_sizes[1];
    const int E2 = in_sizes[3];

    float* h1;
    __half *A, *Bhi, *Blo;
    int *hist, *off1, *cur1, *off2, *cur2, *ss1, *ss2;
    cudaGetSymbolAddress((void**)&h1,   g_h1);
    cudaGetSymbolAddress((void**)&A,    g_A);
    cudaGetSymbolAddress((void**)&Bhi,  g_Bhi);
    cudaGetSymbolAddress((void**)&Blo,  g_Blo);
    cudaGetSymbolAddress((void**)&hist, g_hist);
    cudaGetSymbolAddress((void**)&off1, g_off1);
    cudaGetSymbolAddress((void**)&cur1, g_cur1);
    cudaGetSymbolAddress((void**)&off2, g_off2);
    cudaGetSymbolAddress((void**)&cur2, g_cur2);
    cudaGetSymbolAddress((void**)&ss1,  g_ss1);
    cudaGetSymbolAddress((void**)&ss2,  g_ss2);

    float* out = (float*)d_out;

    const int SMEM_GEMM = 16384 + 2 * 32768;   // 80KB
    cudaFuncSetAttribute(gemm_fp16, cudaFuncAttributeMaxDynamicSharedMemorySize, SMEM_GEMM);

    const int E4 = 256 * 4;

    // launch idx:
    cudaMemsetAsync(hist, 0, (N1C + N2C) * sizeof(int));                        // 0
    hist_kernel<<<(E1 + E4 - 1) / E4, 256>>>(dst1, E1, hist);                   // 1
    scan_kernel<<<1, 1024>>>(hist, N1C, off1, cur1);                            // 2
    reorder_kernel<<<(E1 + E4 - 1) / E4, 256>>>(src1, dst1, E1, cur1, ss1);     // 3
    agg_mean<<<(N1C + 7) / 8, 256>>>(x, x, ss1, off1, A, N1C);                  // 4 <- ncu
    pack_B<<<(2 * 512 * 64 + 255) / 256, 256>>>(W_l1, W_r1, W_l2, W_r2, Bhi, Blo);  // 5
    {
        dim3 grid((N1C + FBM - 1) / FBM, 2);                                    // 6
        gemm_fp16<<<grid, 256, SMEM_GEMM>>>(A, Bhi, Blo, b1, a1, h1, N1C);
    }

    // ---------------- layer 2 ----------------
    hist_kernel<<<(E2 + E4 - 1) / E4, 256>>>(dst2, E2, hist + N1C);             // 7
    scan_kernel<<<1, 1024>>>(hist + N1C, N2C, off2, cur2);                      // 8
    reorder_kernel<<<(E2 + E4 - 1) / E4, 256>>>(src2, dst2, E2, cur2, ss2);     // 9
    agg_mean<<<(N2C + 7) / 8, 256>>>(h1, h1, ss2, off2, A, N2C);                // 10
    {
        dim3 grid((N2C + FBM - 1) / FBM, 2);                                    // 11
        gemm_fp16<<<grid, 256, SMEM_GEMM>>>(A, Bhi + 512 * 256, Blo + 512 * 256, b2, a2, out, N2C);
    }
}